// round 11
// baseline (speedup 1.0000x reference)
#include <cuda_runtime.h>
#include <cuda_fp16.h>
#include <cstdint>

#define C_DIM  64
#define K_DIM  1024
#define HW     4096
#define NPOS   131072
#define MTILE  64                  // positions per CTA
#define BTILE  64                  // codes per smem tile
#define NBT    (K_DIM / BTILE)     // 16 total tiles; 8 per K-half
#define NTHREADS 128
#define INV2048 4.8828125e-4f

// ---------- static device scratch ----------
__device__ char     g_ebuf[NBT * 16384];     // pre-built smem tile images [t][hi 8K|lo 8K]
__device__ float    g_nrm[K_DIM];
__device__ unsigned long long g_best[NPOS];  // (flip(dist)<<32)|k, merged via atomicMin

// ---------- fused prep: norms + fp16 hi/lo split + tile-image scatter ----------
__global__ void prep(const float* __restrict__ emb) {
    const int t = threadIdx.x;
    const int k = blockIdx.x * 64 + (t >> 2);
    const int q = t & 3;
    const float4* src = (const float4*)(emb + (size_t)k * C_DIM + q * 16);
    float4 v0 = src[0], v1 = src[1], v2 = src[2], v3 = src[3];
    float w[16] = { v0.x, v0.y, v0.z, v0.w, v1.x, v1.y, v1.z, v1.w,
                    v2.x, v2.y, v2.z, v2.w, v3.x, v3.y, v3.z, v3.w };

    float s = 0.f;
#pragma unroll
    for (int i = 0; i < 16; i++) s += w[i] * w[i];
    s += __shfl_xor_sync(0xFFFFFFFFu, s, 1);
    s += __shfl_xor_sync(0xFFFFFFFFu, s, 2);
    if (q == 0) g_nrm[k] = s;

    const int tt = k >> 6, n = k & 63;
    const int nt2 = n >> 4, rr = n & 15, slot = rr >> 3, r = rr & 7;
    char* base = g_ebuf + (size_t)tt * 16384 + nt2 * 2048 + r * 256
               + ((q ^ (r & 3)) * 64) + slot * 8;
#pragma unroll
    for (int c0 = 0; c0 < 4; c0++) {
        float a0 = w[2 * c0], a1 = w[2 * c0 + 1], a2 = w[2 * c0 + 8], a3 = w[2 * c0 + 9];
        __half h0 = __float2half_rn(a0), h1 = __float2half_rn(a1);
        __half h2 = __float2half_rn(a2), h3 = __float2half_rn(a3);
        __half hv[4] = { h0, h1, h2, h3 };
        __half lv[4] = { __float2half_rn((a0 - __half2float(h0)) * 2048.f),
                         __float2half_rn((a1 - __half2float(h1)) * 2048.f),
                         __float2half_rn((a2 - __half2float(h2)) * 2048.f),
                         __float2half_rn((a3 - __half2float(h3)) * 2048.f) };
        *(uint64_t*)(base + c0 * 16)        = *(uint64_t*)hv;
        *(uint64_t*)(base + c0 * 16 + 8192) = *(uint64_t*)lv;
    }
}

// ---------- init: reset merge keys (must run every replay) ----------
__global__ void init_best() {
    int i = blockIdx.x * 256 + threadIdx.x;
    g_best[i] = 0xFFFFFFFFFFFFFFFFull;
}

// ---------- mma + cp.async ----------
__device__ __forceinline__ void mma16(float* d, uint4 a, uint32_t bx, uint32_t by) {
    asm volatile("mma.sync.aligned.m16n8k16.row.col.f32.f16.f16.f32 "
        "{%0,%1,%2,%3}, {%4,%5,%6,%7}, {%8,%9}, {%0,%1,%2,%3};"
        : "+f"(d[0]), "+f"(d[1]), "+f"(d[2]), "+f"(d[3])
        : "r"(a.x), "r"(a.z), "r"(a.y), "r"(a.w), "r"(bx), "r"(by));
}
__device__ __forceinline__ void cp16cp(void* dst_smem, const void* src) {
    uint32_t d;
    asm("{ .reg .u64 t; cvta.to.shared.u64 t, %1; cvt.u32.u64 %0, t; }" : "=r"(d) : "l"(dst_smem));
    asm volatile("cp.async.cg.shared.global [%0], [%1], 16;" :: "r"(d), "l"(src) : "memory");
}
#define CP_COMMIT() asm volatile("cp.async.commit_group;" ::: "memory")
#define CP_WAIT1()  asm volatile("cp.async.wait_group 1;" ::: "memory")
#define CP_WAIT0()  asm volatile("cp.async.wait_group 0;" ::: "memory")

// smem: 3 x 16KB tile ring, norms (512 f32) at 48K; ztr overlays buf2 at startup
#define SM_NRM  49152
#define SM_TOT  51200

__device__ __forceinline__ void copy_tile(int t, char* dst, int tid) {
    const char* src = g_ebuf + (size_t)t * 16384;
#pragma unroll
    for (int i = 0; i < 8; i++) {
        int u = (tid + i * NTHREADS) * 16;
        cp16cp(dst + u, src + u);
    }
}

__device__ __forceinline__ uint32_t packh2(float a, float b) {
    __half2 h = __floats2half2_rn(a, b);
    return *(uint32_t*)&h;
}
__device__ __forceinline__ uint32_t flipf(float d) {
    uint32_t u = __float_as_uint(d);
    return u ^ (((int)u >> 31) | 0x80000000u);
}

// ---------- main kernel: one (position slab, K-half) per CTA ----------
__global__ __launch_bounds__(NTHREADS, 4)
void vq_mma(const float* __restrict__ z_e)
{
    extern __shared__ char smem[];
    float* nsm = (float*)(smem + SM_NRM);
    float* ztr = (float*)(smem + 32768);           // overlays buf2

    const int tid  = threadIdx.x;
    const int lane = tid & 31, warp = tid >> 5;
    const int c0   = lane & 3, r = lane >> 2;
    const int pt   = blockIdx.x >> 1;              // position tile
    const int kh   = blockIdx.x & 1;               // K half
    const int t0   = kh * 8;                       // first absolute tile
    const int p0   = pt * MTILE;
    const int b    = p0 >> 12, hw0 = p0 & (HW - 1);

    // this half's norms -> smem (512 floats)
    ((float4*)nsm)[tid] = ((const float4*)(g_nrm + kh * 512))[tid];

    // prologue: copies of tiles t0, t0+1 into buf0, buf1 (independent of ztr)
    copy_tile(t0,     smem,         tid); CP_COMMIT();
    copy_tile(t0 + 1, smem + 16384, tid); CP_COMMIT();

    // z slab: ztr[c][x] = -2 * z[b, c, hw0 + x]
    {
        const float* zsrc = z_e + (size_t)b * C_DIM * HW + hw0;
#pragma unroll
        for (int i = 0; i < 8; i++) {
            int idx = tid + i * NTHREADS;
            int c = idx >> 4, x4 = idx & 15;
            float4 v = *(const float4*)(zsrc + (size_t)c * HW + x4 * 4);
            v.x *= -2.f; v.y *= -2.f; v.z *= -2.f; v.w *= -2.f;
            *(float4*)(ztr + c * 64 + x4 * 4) = v;
        }
    }
    __syncthreads();

    // A fragments in-register
    uint4 Ah[4], Al[4];
    {
        const int pa = warp * 16 + r, pb = pa + 8;
#pragma unroll
        for (int ks = 0; ks < 4; ks++) {
            int k0 = 16 * ks + 2 * c0;
            float v0 = ztr[(k0    ) * 64 + pa], v1 = ztr[(k0 + 1) * 64 + pa];
            float v2 = ztr[(k0 + 8) * 64 + pa], v3 = ztr[(k0 + 9) * 64 + pa];
            float v4 = ztr[(k0    ) * 64 + pb], v5 = ztr[(k0 + 1) * 64 + pb];
            float v6 = ztr[(k0 + 8) * 64 + pb], v7 = ztr[(k0 + 9) * 64 + pb];
            float h0 = __half2float(__float2half_rn(v0));
            float h1 = __half2float(__float2half_rn(v1));
            float h2 = __half2float(__float2half_rn(v2));
            float h3 = __half2float(__float2half_rn(v3));
            float h4 = __half2float(__float2half_rn(v4));
            float h5 = __half2float(__float2half_rn(v5));
            float h6 = __half2float(__float2half_rn(v6));
            float h7 = __half2float(__float2half_rn(v7));
            Ah[ks].x = packh2(h0, h1); Ah[ks].y = packh2(h2, h3);
            Ah[ks].z = packh2(h4, h5); Ah[ks].w = packh2(h6, h7);
            Al[ks].x = packh2((v0 - h0) * 2048.f, (v1 - h1) * 2048.f);
            Al[ks].y = packh2((v2 - h2) * 2048.f, (v3 - h3) * 2048.f);
            Al[ks].z = packh2((v4 - h4) * 2048.f, (v5 - h5) * 2048.f);
            Al[ks].w = packh2((v6 - h6) * 2048.f, (v7 - h7) * 2048.f);
        }
    }

    int kk[4];
#pragma unroll
    for (int ks = 0; ks < 4; ks++) kk[ks] = ((ks ^ (r & 3)) * 64) + c0 * 16;

    float bestA = 3.402823466e+38f, bestB = 3.402823466e+38f;
    int   kA = 0, kB = 0;

    // 3-stage mainloop: one barrier per tile
    for (int tl = 0; tl < 8; tl++) {
        if (tl < 7) { CP_WAIT1(); } else { CP_WAIT0(); }
        __syncthreads();                            // tile tl visible; buf (tl+2)%3 free
        if (tl + 2 < 8) {
            copy_tile(t0 + tl + 2, smem + (size_t)((tl + 2) % 3) * 16384, tid);
            CP_COMMIT();
        }

        const char* buf = smem + (size_t)(tl % 3) * 16384;

#pragma unroll
        for (int nt2 = 0; nt2 < 4; nt2++) {
            const int  nl = tl * BTILE + nt2 * 16;  // index into this half's norms
            const char* bA = buf + nt2 * 2048 + r * 256;

            float2 nv0 = *(const float2*)(nsm + nl + 2 * c0);
            float2 nv1 = *(const float2*)(nsm + nl + 8 + 2 * c0);
            float hh0[4] = { nv0.x, nv0.y, nv0.x, nv0.y };
            float hh1[4] = { nv1.x, nv1.y, nv1.x, nv1.y };
            float x0[4] = {0,0,0,0}, x1[4] = {0,0,0,0};

#pragma unroll
            for (int ks = 0; ks < 4; ks++) {
                uint4 bh = *(const uint4*)(bA + kk[ks]);
                uint4 bl = *(const uint4*)(bA + kk[ks] + 8192);
                mma16(hh0, Ah[ks], bh.x, bh.y);
                mma16(hh1, Ah[ks], bh.z, bh.w);
                mma16(x0,  Ah[ks], bl.x, bl.y);
                mma16(x0,  Al[ks], bh.x, bh.y);
                mma16(x1,  Ah[ks], bl.z, bl.w);
                mma16(x1,  Al[ks], bh.z, bh.w);
            }

            const int n0 = kh * 512 + nl;           // absolute code base
            {
                int e = n0 + 2 * c0;
                float d0 = fmaf(x0[0], INV2048, hh0[0]);
                float d1 = fmaf(x0[1], INV2048, hh0[1]);
                float d2 = fmaf(x0[2], INV2048, hh0[2]);
                float d3 = fmaf(x0[3], INV2048, hh0[3]);
                if (d0 < bestA) { bestA = d0; kA = e; }
                if (d1 < bestA) { bestA = d1; kA = e + 1; }
                if (d2 < bestB) { bestB = d2; kB = e; }
                if (d3 < bestB) { bestB = d3; kB = e + 1; }
            }
            {
                int e = n0 + 8 + 2 * c0;
                float d0 = fmaf(x1[0], INV2048, hh1[0]);
                float d1 = fmaf(x1[1], INV2048, hh1[1]);
                float d2 = fmaf(x1[2], INV2048, hh1[2]);
                float d3 = fmaf(x1[3], INV2048, hh1[3]);
                if (d0 < bestA) { bestA = d0; kA = e; }
                if (d1 < bestA) { bestA = d1; kA = e + 1; }
                if (d2 < bestB) { bestB = d2; kB = e; }
                if (d3 < bestB) { bestB = d3; kB = e + 1; }
            }
        }
    }

    // c0-lane reduce (tie-break smallest k), then merge via atomicMin
#pragma unroll
    for (int off = 1; off <= 2; off <<= 1) {
        float vb = __shfl_xor_sync(0xFFFFFFFFu, bestA, off);
        int   vk = __shfl_xor_sync(0xFFFFFFFFu, kA, off);
        if (vb < bestA || (vb == bestA && vk < kA)) { bestA = vb; kA = vk; }
        vb = __shfl_xor_sync(0xFFFFFFFFu, bestB, off);
        vk = __shfl_xor_sync(0xFFFFFFFFu, kB, off);
        if (vb < bestB || (vb == bestB && vk < kB)) { bestB = vb; kB = vk; }
    }
    if (c0 == 0) {
        unsigned long long keyA = ((unsigned long long)flipf(bestA) << 32) | (uint32_t)kA;
        unsigned long long keyB = ((unsigned long long)flipf(bestB) << 32) | (uint32_t)kB;
        atomicMin(&g_best[p0 + warp * 16 + r],     keyA);
        atomicMin(&g_best[p0 + warp * 16 + r + 8], keyB);
    }
}

// ---------- gather: winners -> [B, C, H, W] ----------
__global__ __launch_bounds__(NTHREADS)
void gather(const float* __restrict__ emb, float* __restrict__ out)
{
    const int tid = threadIdx.x;
    const int p0  = blockIdx.x * MTILE;
    const int b   = p0 >> 12, hw0 = p0 & (HW - 1);
    const int pl  = tid & (MTILE - 1);
    const int cb  = (tid >> 6) * 32;
    const int k   = (uint32_t)g_best[p0 + pl];
    const float4* ev = (const float4*)(emb + (size_t)k * C_DIM + cb);
    float* op = out + (size_t)b * C_DIM * HW + hw0 + pl;
#pragma unroll
    for (int c4 = 0; c4 < 8; c4++) {
        float4 v = ev[c4];
        op[(size_t)(cb + c4 * 4 + 0) * HW] = v.x;
        op[(size_t)(cb + c4 * 4 + 1) * HW] = v.y;
        op[(size_t)(cb + c4 * 4 + 2) * HW] = v.z;
        op[(size_t)(cb + c4 * 4 + 3) * HW] = v.w;
    }
}

// ---------- launch ----------
extern "C" void kernel_launch(void* const* d_in, const int* in_sizes, int n_in,
                              void* d_out, int out_size)
{
    const float* z_e = (const float*)d_in[0];   // [32, 64, 64, 64]
    const float* emb = (const float*)d_in[1];   // [1024, 64]
    float*       out = (float*)d_out;

    cudaFuncSetAttribute(vq_mma, cudaFuncAttributeMaxDynamicSharedMemorySize, SM_TOT);

    prep<<<K_DIM / 64, 256>>>(emb);
    init_best<<<NPOS / 256, 256>>>();
    vq_mma<<<(NPOS / MTILE) * 2, NTHREADS, SM_TOT>>>(z_e);
    gather<<<NPOS / MTILE, NTHREADS>>>(emb, out);
}

// round 12
// speedup vs baseline: 1.1319x; 1.1319x over previous
#include <cuda_runtime.h>
#include <cuda_fp16.h>
#include <cstdint>

#define C_DIM  64
#define K_DIM  1024
#define HW     4096
#define NPOS   131072
#define MTILE  128                 // positions per CTA (2 x M16 groups per warp)
#define BTILE  64                  // codes per smem tile
#define NBT    (K_DIM / BTILE)     // 16
#define NTHREADS 128
#define INV2048 4.8828125e-4f
#define ZP     132                 // ztr pitch (conflict-free frag build)

// ---------- static device scratch ----------
__device__ char  g_ebuf[NBT * 16384];   // pre-built smem tile images [t][hi 8K|lo 8K]
__device__ float g_nrm[K_DIM];

// ---------- fused prep: norms + fp16 hi/lo split + tile-image scatter ----------
__global__ void prep(const float* __restrict__ emb) {
    const int t = threadIdx.x;
    const int k = blockIdx.x * 64 + (t >> 2);
    const int q = t & 3;
    const float4* src = (const float4*)(emb + (size_t)k * C_DIM + q * 16);
    float4 v0 = src[0], v1 = src[1], v2 = src[2], v3 = src[3];
    float w[16] = { v0.x, v0.y, v0.z, v0.w, v1.x, v1.y, v1.z, v1.w,
                    v2.x, v2.y, v2.z, v2.w, v3.x, v3.y, v3.z, v3.w };

    float s = 0.f;
#pragma unroll
    for (int i = 0; i < 16; i++) s += w[i] * w[i];
    s += __shfl_xor_sync(0xFFFFFFFFu, s, 1);
    s += __shfl_xor_sync(0xFFFFFFFFu, s, 2);
    if (q == 0) g_nrm[k] = s;

    const int tt = k >> 6, n = k & 63;
    const int nt2 = n >> 4, rr = n & 15, slot = rr >> 3, r = rr & 7;
    char* base = g_ebuf + (size_t)tt * 16384 + nt2 * 2048 + r * 256
               + ((q ^ (r & 3)) * 64) + slot * 8;
#pragma unroll
    for (int c0 = 0; c0 < 4; c0++) {
        float a0 = w[2 * c0], a1 = w[2 * c0 + 1], a2 = w[2 * c0 + 8], a3 = w[2 * c0 + 9];
        __half h0 = __float2half_rn(a0), h1 = __float2half_rn(a1);
        __half h2 = __float2half_rn(a2), h3 = __float2half_rn(a3);
        __half hv[4] = { h0, h1, h2, h3 };
        __half lv[4] = { __float2half_rn((a0 - __half2float(h0)) * 2048.f),
                         __float2half_rn((a1 - __half2float(h1)) * 2048.f),
                         __float2half_rn((a2 - __half2float(h2)) * 2048.f),
                         __float2half_rn((a3 - __half2float(h3)) * 2048.f) };
        *(uint64_t*)(base + c0 * 16)        = *(uint64_t*)hv;
        *(uint64_t*)(base + c0 * 16 + 8192) = *(uint64_t*)lv;
    }
}

// ---------- mma + cp.async ----------
__device__ __forceinline__ void mma16(float* d, uint4 a, uint32_t bx, uint32_t by) {
    asm volatile("mma.sync.aligned.m16n8k16.row.col.f32.f16.f16.f32 "
        "{%0,%1,%2,%3}, {%4,%5,%6,%7}, {%8,%9}, {%0,%1,%2,%3};"
        : "+f"(d[0]), "+f"(d[1]), "+f"(d[2]), "+f"(d[3])
        : "r"(a.x), "r"(a.z), "r"(a.y), "r"(a.w), "r"(bx), "r"(by));
}
__device__ __forceinline__ void cp16cp(void* dst_smem, const void* src) {
    uint32_t d;
    asm("{ .reg .u64 t; cvta.to.shared.u64 t, %1; cvt.u32.u64 %0, t; }" : "=r"(d) : "l"(dst_smem));
    asm volatile("cp.async.cg.shared.global [%0], [%1], 16;" :: "r"(d), "l"(src) : "memory");
}
#define CP_COMMIT() asm volatile("cp.async.commit_group;" ::: "memory")
#define CP_WAIT1()  asm volatile("cp.async.wait_group 1;" ::: "memory")
#define CP_WAIT0()  asm volatile("cp.async.wait_group 0;" ::: "memory")

// smem map: bufs 3 x 16KB at 0; ztr (64 x 132 floats = 33792B) overlays 16384..50176
// during startup; norms at 50176 (4KB); idx at 54272 (512B)
#define SM_NRM  50176
#define SM_IDX  54272
#define SM_TOT  54784

__device__ __forceinline__ void copy_tile(int t, char* dst, int tid) {
    const char* src = g_ebuf + (size_t)t * 16384;
#pragma unroll
    for (int i = 0; i < 8; i++) {
        int u = (tid + i * NTHREADS) * 16;
        cp16cp(dst + u, src + u);
    }
}

__device__ __forceinline__ uint32_t packh2(float a, float b) {
    __half2 h = __floats2half2_rn(a, b);
    return *(uint32_t*)&h;
}

// build one M16 A-fragment pair (hi/lo) for base position row pa
__device__ __forceinline__ void build_frag(const float* ztr, int pa, int c0,
                                           uint4* Ah, uint4* Al) {
    const int pb = pa + 8;
#pragma unroll
    for (int ks = 0; ks < 4; ks++) {
        int k0 = 16 * ks + 2 * c0;
        float v0 = ztr[(k0    ) * ZP + pa], v1 = ztr[(k0 + 1) * ZP + pa];
        float v2 = ztr[(k0 + 8) * ZP + pa], v3 = ztr[(k0 + 9) * ZP + pa];
        float v4 = ztr[(k0    ) * ZP + pb], v5 = ztr[(k0 + 1) * ZP + pb];
        float v6 = ztr[(k0 + 8) * ZP + pb], v7 = ztr[(k0 + 9) * ZP + pb];
        float h0 = __half2float(__float2half_rn(v0));
        float h1 = __half2float(__float2half_rn(v1));
        float h2 = __half2float(__float2half_rn(v2));
        float h3 = __half2float(__float2half_rn(v3));
        float h4 = __half2float(__float2half_rn(v4));
        float h5 = __half2float(__float2half_rn(v5));
        float h6 = __half2float(__float2half_rn(v6));
        float h7 = __half2float(__float2half_rn(v7));
        Ah[ks].x = packh2(h0, h1); Ah[ks].y = packh2(h2, h3);
        Ah[ks].z = packh2(h4, h5); Ah[ks].w = packh2(h6, h7);
        Al[ks].x = packh2((v0 - h0) * 2048.f, (v1 - h1) * 2048.f);
        Al[ks].y = packh2((v2 - h2) * 2048.f, (v3 - h3) * 2048.f);
        Al[ks].z = packh2((v4 - h4) * 2048.f, (v5 - h5) * 2048.f);
        Al[ks].w = packh2((v6 - h6) * 2048.f, (v7 - h7) * 2048.f);
    }
}

// ---------- main kernel ----------
__global__ __launch_bounds__(NTHREADS, 3)
void vq_mma(const float* __restrict__ z_e, const float* __restrict__ emb,
            float* __restrict__ out)
{
    extern __shared__ char smem[];
    float* nsm  = (float*)(smem + SM_NRM);
    int*   sIdx = (int*)(smem + SM_IDX);
    float* ztr  = (float*)(smem + 16384);          // [64 dims][ZP]

    const int tid  = threadIdx.x;
    const int lane = tid & 31, warp = tid >> 5;
    const int c0   = lane & 3, r = lane >> 2;
    const int p0   = blockIdx.x * MTILE;
    const int b    = p0 >> 12, hw0 = p0 & (HW - 1);

    // norms -> smem (1024 floats)
    ((float4*)nsm)[tid]            = ((const float4*)g_nrm)[tid];
    ((float4*)nsm)[tid + NTHREADS] = ((const float4*)g_nrm)[tid + NTHREADS];

    // tile 0 -> buf0 (no overlap with ztr)
    copy_tile(0, smem, tid);
    CP_COMMIT();

    // z slab: ztr[c][x] = -2 * z[b, c, hw0 + x], x in 0..127
    {
        const float* zsrc = z_e + (size_t)b * C_DIM * HW + hw0;
#pragma unroll
        for (int i = 0; i < 16; i++) {
            int idx = tid + i * NTHREADS;          // 0..2047 float4 units
            int c = idx >> 5, x4 = idx & 31;
            float4 v = *(const float4*)(zsrc + (size_t)c * HW + x4 * 4);
            v.x *= -2.f; v.y *= -2.f; v.z *= -2.f; v.w *= -2.f;
            *(float4*)(ztr + c * ZP + x4 * 4) = v;
        }
    }
    __syncthreads();

    // two A-fragment sets per warp: positions warp*16.. and 64+warp*16..
    uint4 AhA[4], AlA[4], AhB[4], AlB[4];
    build_frag(ztr, warp * 16 + r,      c0, AhA, AlA);
    build_frag(ztr, 64 + warp * 16 + r, c0, AhB, AlB);
    __syncthreads();                               // everyone done with ztr

    // tile 1 -> buf1 (ztr region now dead)
    copy_tile(1, smem + 16384, tid);
    CP_COMMIT();

    int kk[4];
#pragma unroll
    for (int ks = 0; ks < 4; ks++) kk[ks] = ((ks ^ (r & 3)) * 64) + c0 * 16;

    float bA0 = 3.402823466e+38f, bB0 = bA0, bA1 = bA0, bB1 = bA0;
    int   kA0 = 0, kB0 = 0, kA1 = 0, kB1 = 0;

    for (int tl = 0; tl < NBT; tl++) {
        if (tl < NBT - 1) { CP_WAIT1(); } else { CP_WAIT0(); }
        __syncthreads();                           // tile tl ready; buf (tl+2)%3 free
        if (tl + 2 < NBT) {
            copy_tile(tl + 2, smem + (size_t)((tl + 2) % 3) * 16384, tid);
            CP_COMMIT();
        }

        const char* buf = smem + (size_t)(tl % 3) * 16384;

#pragma unroll
        for (int nt2 = 0; nt2 < 4; nt2++) {
            const int  n0 = tl * BTILE + nt2 * 16;
            const char* bA = buf + nt2 * 2048 + r * 256;

            float2 nv0 = *(const float2*)(nsm + n0 + 2 * c0);
            float2 nv1 = *(const float2*)(nsm + n0 + 8 + 2 * c0);
            float hhA0[4] = { nv0.x, nv0.y, nv0.x, nv0.y };
            float hhA1[4] = { nv1.x, nv1.y, nv1.x, nv1.y };
            float hhB0[4] = { nv0.x, nv0.y, nv0.x, nv0.y };
            float hhB1[4] = { nv1.x, nv1.y, nv1.x, nv1.y };
            float xA0[4] = {0,0,0,0}, xA1[4] = {0,0,0,0};
            float xB0[4] = {0,0,0,0}, xB1[4] = {0,0,0,0};

#pragma unroll
            for (int ks = 0; ks < 4; ks++) {
                uint4 bh = *(const uint4*)(bA + kk[ks]);
                uint4 bl = *(const uint4*)(bA + kk[ks] + 8192);
                mma16(hhA0, AhA[ks], bh.x, bh.y);
                mma16(hhA1, AhA[ks], bh.z, bh.w);
                mma16(xA0,  AhA[ks], bl.x, bl.y);
                mma16(xA0,  AlA[ks], bh.x, bh.y);
                mma16(xA1,  AhA[ks], bl.z, bl.w);
                mma16(xA1,  AlA[ks], bh.z, bh.w);
                mma16(hhB0, AhB[ks], bh.x, bh.y);
                mma16(hhB1, AhB[ks], bh.z, bh.w);
                mma16(xB0,  AhB[ks], bl.x, bl.y);
                mma16(xB0,  AlB[ks], bh.x, bh.y);
                mma16(xB1,  AhB[ks], bl.z, bl.w);
                mma16(xB1,  AlB[ks], bh.z, bh.w);
            }

            // dist = norm + hh + x * 2^-11 ; ascending k, strict <
#pragma unroll
            for (int g = 0; g < 2; g++) {
                float* hh0 = g ? hhB0 : hhA0;
                float* hh1 = g ? hhB1 : hhA1;
                float* x0  = g ? xB0  : xA0;
                float* x1  = g ? xB1  : xA1;
                float& bA_ = g ? bA1 : bA0;  int& kA_ = g ? kA1 : kA0;
                float& bB_ = g ? bB1 : bB0;  int& kB_ = g ? kB1 : kB0;
                {
                    int e = n0 + 2 * c0;
                    float d0 = fmaf(x0[0], INV2048, hh0[0]);
                    float d1 = fmaf(x0[1], INV2048, hh0[1]);
                    float d2 = fmaf(x0[2], INV2048, hh0[2]);
                    float d3 = fmaf(x0[3], INV2048, hh0[3]);
                    if (d0 < bA_) { bA_ = d0; kA_ = e; }
                    if (d1 < bA_) { bA_ = d1; kA_ = e + 1; }
                    if (d2 < bB_) { bB_ = d2; kB_ = e; }
                    if (d3 < bB_) { bB_ = d3; kB_ = e + 1; }
                }
                {
                    int e = n0 + 8 + 2 * c0;
                    float d0 = fmaf(x1[0], INV2048, hh1[0]);
                    float d1 = fmaf(x1[1], INV2048, hh1[1]);
                    float d2 = fmaf(x1[2], INV2048, hh1[2]);
                    float d3 = fmaf(x1[3], INV2048, hh1[3]);
                    if (d0 < bA_) { bA_ = d0; kA_ = e; }
                    if (d1 < bA_) { bA_ = d1; kA_ = e + 1; }
                    if (d2 < bB_) { bB_ = d2; kB_ = e; }
                    if (d3 < bB_) { bB_ = d3; kB_ = e + 1; }
                }
            }
        }
    }

    // c0-lane reduce (tie-break smallest k)
#pragma unroll
    for (int off = 1; off <= 2; off <<= 1) {
        float vb; int vk;
        vb = __shfl_xor_sync(0xFFFFFFFFu, bA0, off); vk = __shfl_xor_sync(0xFFFFFFFFu, kA0, off);
        if (vb < bA0 || (vb == bA0 && vk < kA0)) { bA0 = vb; kA0 = vk; }
        vb = __shfl_xor_sync(0xFFFFFFFFu, bB0, off); vk = __shfl_xor_sync(0xFFFFFFFFu, kB0, off);
        if (vb < bB0 || (vb == bB0 && vk < kB0)) { bB0 = vb; kB0 = vk; }
        vb = __shfl_xor_sync(0xFFFFFFFFu, bA1, off); vk = __shfl_xor_sync(0xFFFFFFFFu, kA1, off);
        if (vb < bA1 || (vb == bA1 && vk < kA1)) { bA1 = vb; kA1 = vk; }
        vb = __shfl_xor_sync(0xFFFFFFFFu, bB1, off); vk = __shfl_xor_sync(0xFFFFFFFFu, kB1, off);
        if (vb < bB1 || (vb == bB1 && vk < kB1)) { bB1 = vb; kB1 = vk; }
    }
    if (c0 == 0) {
        sIdx[warp * 16 + r]          = kA0;
        sIdx[warp * 16 + r + 8]      = kB0;
        sIdx[64 + warp * 16 + r]     = kA1;
        sIdx[64 + warp * 16 + r + 8] = kB1;
    }
    __syncthreads();

    // gather winning codes (original fp32 emb) and scatter to [B,C,H,W]
    {
        const int pl = tid;                        // one position per thread
        const int k  = sIdx[pl];
        const float4* ev = (const float4*)(emb + (size_t)k * C_DIM);
        float* op = out + (size_t)b * C_DIM * HW + hw0 + pl;
#pragma unroll
        for (int c4 = 0; c4 < 16; c4++) {
            float4 v = ev[c4];
            op[(size_t)(c4 * 4 + 0) * HW] = v.x;
            op[(size_t)(c4 * 4 + 1) * HW] = v.y;
            op[(size_t)(c4 * 4 + 2) * HW] = v.z;
            op[(size_t)(c4 * 4 + 3) * HW] = v.w;
        }
    }
}

// ---------- launch ----------
extern "C" void kernel_launch(void* const* d_in, const int* in_sizes, int n_in,
                              void* d_out, int out_size)
{
    const float* z_e = (const float*)d_in[0];   // [32, 64, 64, 64]
    const float* emb = (const float*)d_in[1];   // [1024, 64]
    float*       out = (float*)d_out;

    cudaFuncSetAttribute(vq_mma, cudaFuncAttributeMaxDynamicSharedMemorySize, SM_TOT);

    prep<<<K_DIM / 64, 256>>>(emb);
    vq_mma<<<NPOS / MTILE, NTHREADS, SM_TOT>>>(z_e, emb, out);
}

// round 13
// speedup vs baseline: 1.1637x; 1.0281x over previous
#include <cuda_runtime.h>
#include <cuda_fp16.h>
#include <cstdint>

#define C_DIM  64
#define K_DIM  1024
#define HW     4096
#define NPOS   131072
#define MTILE  128                 // positions per CTA (2 x M16 groups per warp)
#define BTILE  64                  // codes per smem tile
#define NBT    (K_DIM / BTILE)     // 16
#define NTHREADS 128
#define INV2048 4.8828125e-4f
#define ZP     132                 // ztr pitch (conflict-free frag build)

// ---------- static device scratch ----------
__device__ __align__(128) char g_ebuf[NBT * 16384];  // smem tile images [t][hi 8K|lo 8K]
__device__ float g_nrm[K_DIM];

// ---------- fused prep: norms + fp16 hi/lo split + tile-image scatter ----------
__global__ void prep(const float* __restrict__ emb) {
    const int t = threadIdx.x;
    const int k = blockIdx.x * 64 + (t >> 2);
    const int q = t & 3;
    const float4* src = (const float4*)(emb + (size_t)k * C_DIM + q * 16);
    float4 v0 = src[0], v1 = src[1], v2 = src[2], v3 = src[3];
    float w[16] = { v0.x, v0.y, v0.z, v0.w, v1.x, v1.y, v1.z, v1.w,
                    v2.x, v2.y, v2.z, v2.w, v3.x, v3.y, v3.z, v3.w };

    float s = 0.f;
#pragma unroll
    for (int i = 0; i < 16; i++) s += w[i] * w[i];
    s += __shfl_xor_sync(0xFFFFFFFFu, s, 1);
    s += __shfl_xor_sync(0xFFFFFFFFu, s, 2);
    if (q == 0) g_nrm[k] = s;

    const int tt = k >> 6, n = k & 63;
    const int nt2 = n >> 4, rr = n & 15, slot = rr >> 3, r = rr & 7;
    char* base = g_ebuf + (size_t)tt * 16384 + nt2 * 2048 + r * 256
               + ((q ^ (r & 3)) * 64) + slot * 8;
#pragma unroll
    for (int c0 = 0; c0 < 4; c0++) {
        float a0 = w[2 * c0], a1 = w[2 * c0 + 1], a2 = w[2 * c0 + 8], a3 = w[2 * c0 + 9];
        __half h0 = __float2half_rn(a0), h1 = __float2half_rn(a1);
        __half h2 = __float2half_rn(a2), h3 = __float2half_rn(a3);
        __half hv[4] = { h0, h1, h2, h3 };
        __half lv[4] = { __float2half_rn((a0 - __half2float(h0)) * 2048.f),
                         __float2half_rn((a1 - __half2float(h1)) * 2048.f),
                         __float2half_rn((a2 - __half2float(h2)) * 2048.f),
                         __float2half_rn((a3 - __half2float(h3)) * 2048.f) };
        *(uint64_t*)(base + c0 * 16)        = *(uint64_t*)hv;
        *(uint64_t*)(base + c0 * 16 + 8192) = *(uint64_t*)lv;
    }
}

// ---------- mma + bulk-copy helpers ----------
__device__ __forceinline__ void mma16(float* d, uint4 a, uint32_t bx, uint32_t by) {
    asm volatile("mma.sync.aligned.m16n8k16.row.col.f32.f16.f16.f32 "
        "{%0,%1,%2,%3}, {%4,%5,%6,%7}, {%8,%9}, {%0,%1,%2,%3};"
        : "+f"(d[0]), "+f"(d[1]), "+f"(d[2]), "+f"(d[3])
        : "r"(a.x), "r"(a.z), "r"(a.y), "r"(a.w), "r"(bx), "r"(by));
}
__device__ __forceinline__ uint32_t smem_u32(const void* p) {
    uint32_t a;
    asm("{ .reg .u64 t; cvta.to.shared.u64 t, %1; cvt.u32.u64 %0, t; }" : "=r"(a) : "l"(p));
    return a;
}
#define MBAR_INIT(addr, cnt) \
    asm volatile("mbarrier.init.shared.b64 [%0], %1;" :: "r"(addr), "r"(cnt) : "memory")
#define MBAR_EXPECT_TX(addr, bytes) \
    asm volatile("mbarrier.arrive.expect_tx.shared.b64 _, [%0], %1;" \
                 :: "r"(addr), "r"((uint32_t)(bytes)) : "memory")
#define MBAR_WAIT(addr, ph) do {                                               \
    uint32_t _a = (addr), _p = (ph), _d;                                       \
    asm volatile("{\n\t.reg .pred p;\n\t"                                      \
        "mbarrier.try_wait.parity.acquire.cta.shared::cta.b64 p, [%1], %2;\n\t"\
        "selp.b32 %0, 1, 0, p;\n\t}"                                           \
        : "=r"(_d) : "r"(_a), "r"(_p) : "memory");                             \
    while (!_d) {                                                              \
        asm volatile("{\n\t.reg .pred p;\n\t"                                  \
            "mbarrier.try_wait.parity.acquire.cta.shared::cta.b64 p, [%1], %2, 0x989680;\n\t" \
            "selp.b32 %0, 1, 0, p;\n\t}"                                       \
            : "=r"(_d) : "r"(_a), "r"(_p) : "memory");                         \
    }                                                                          \
} while (0)
__device__ __forceinline__ void bulk_copy(uint32_t dst_smem, const void* src, uint32_t mbar) {
    asm volatile("cp.async.bulk.shared::cluster.global.mbarrier::complete_tx::bytes "
                 "[%0], [%1], %2, [%3];"
                 :: "r"(dst_smem), "l"(src), "r"(16384u), "r"(mbar) : "memory");
}

// smem map: bufs 3 x 16KB at 0; ztr (64 x 132 floats) overlays [16384, 50176);
// norms at 50176 (4KB); idx at 54272 (512B); mbars at 54784
#define SM_NRM  50176
#define SM_IDX  54272
#define SM_MBAR 54784
#define SM_TOT  54848

__device__ __forceinline__ uint32_t packh2(float a, float b) {
    __half2 h = __floats2half2_rn(a, b);
    return *(uint32_t*)&h;
}

// build one M16 A-fragment pair (hi/lo) for base position row pa
__device__ __forceinline__ void build_frag(const float* ztr, int pa, int c0,
                                           uint4* Ah, uint4* Al) {
    const int pb = pa + 8;
#pragma unroll
    for (int ks = 0; ks < 4; ks++) {
        int k0 = 16 * ks + 2 * c0;
        float v0 = ztr[(k0    ) * ZP + pa], v1 = ztr[(k0 + 1) * ZP + pa];
        float v2 = ztr[(k0 + 8) * ZP + pa], v3 = ztr[(k0 + 9) * ZP + pa];
        float v4 = ztr[(k0    ) * ZP + pb], v5 = ztr[(k0 + 1) * ZP + pb];
        float v6 = ztr[(k0 + 8) * ZP + pb], v7 = ztr[(k0 + 9) * ZP + pb];
        float h0 = __half2float(__float2half_rn(v0));
        float h1 = __half2float(__float2half_rn(v1));
        float h2 = __half2float(__float2half_rn(v2));
        float h3 = __half2float(__float2half_rn(v3));
        float h4 = __half2float(__float2half_rn(v4));
        float h5 = __half2float(__float2half_rn(v5));
        float h6 = __half2float(__float2half_rn(v6));
        float h7 = __half2float(__float2half_rn(v7));
        Ah[ks].x = packh2(h0, h1); Ah[ks].y = packh2(h2, h3);
        Ah[ks].z = packh2(h4, h5); Ah[ks].w = packh2(h6, h7);
        Al[ks].x = packh2((v0 - h0) * 2048.f, (v1 - h1) * 2048.f);
        Al[ks].y = packh2((v2 - h2) * 2048.f, (v3 - h3) * 2048.f);
        Al[ks].z = packh2((v4 - h4) * 2048.f, (v5 - h5) * 2048.f);
        Al[ks].w = packh2((v6 - h6) * 2048.f, (v7 - h7) * 2048.f);
    }
}

// ---------- main kernel ----------
__global__ __launch_bounds__(NTHREADS, 3)
void vq_mma(const float* __restrict__ z_e, const float* __restrict__ emb,
            float* __restrict__ out)
{
    extern __shared__ char smem[];
    float* nsm  = (float*)(smem + SM_NRM);
    int*   sIdx = (int*)(smem + SM_IDX);
    float* ztr  = (float*)(smem + 16384);          // [64 dims][ZP]

    const uint32_t sb = smem_u32(smem);
    const uint32_t mb = sb + SM_MBAR;              // 3 mbarriers, 8B each

    const int tid  = threadIdx.x;
    const int lane = tid & 31, warp = tid >> 5;
    const int c0   = lane & 3, r = lane >> 2;
    const int p0   = blockIdx.x * MTILE;
    const int b    = p0 >> 12, hw0 = p0 & (HW - 1);
    const int s    = blockIdx.x & 15;              // tile rotation start

    // mbarrier init + prologue copies (tile s -> buf0). buf0 doesn't overlap ztr.
    if (tid == 0) {
        MBAR_INIT(mb + 0, 1); MBAR_INIT(mb + 8, 1); MBAR_INIT(mb + 16, 1);
        MBAR_EXPECT_TX(mb + 0, 16384);
        bulk_copy(sb, g_ebuf + (size_t)s * 16384, mb + 0);
    }

    // norms -> smem (1024 floats)
    ((float4*)nsm)[tid]            = ((const float4*)g_nrm)[tid];
    ((float4*)nsm)[tid + NTHREADS] = ((const float4*)g_nrm)[tid + NTHREADS];

    // z slab: ztr[c][x] = -2 * z[b, c, hw0 + x], x in 0..127
    {
        const float* zsrc = z_e + (size_t)b * C_DIM * HW + hw0;
#pragma unroll
        for (int i = 0; i < 16; i++) {
            int idx = tid + i * NTHREADS;          // 0..2047 float4 units
            int c = idx >> 5, x4 = idx & 31;
            float4 v = *(const float4*)(zsrc + (size_t)c * HW + x4 * 4);
            v.x *= -2.f; v.y *= -2.f; v.z *= -2.f; v.w *= -2.f;
            *(float4*)(ztr + c * ZP + x4 * 4) = v;
        }
    }
    __syncthreads();                               // ztr ready; mbar init visible

    // two A-fragment sets per warp
    uint4 AhA[4], AlA[4], AhB[4], AlB[4];
    build_frag(ztr, warp * 16 + r,      c0, AhA, AlA);
    build_frag(ztr, 64 + warp * 16 + r, c0, AhB, AlB);
    __syncthreads();                               // everyone done with ztr

    // tile s+1 -> buf1 (ztr region now dead)
    if (tid == 0) {
        MBAR_EXPECT_TX(mb + 8, 16384);
        bulk_copy(sb + 16384, g_ebuf + (size_t)((s + 1) & 15) * 16384, mb + 8);
    }

    int kk[4];
#pragma unroll
    for (int ks = 0; ks < 4; ks++) kk[ks] = ((ks ^ (r & 3)) * 64) + c0 * 16;

    float bA0 = 3.402823466e+38f, bB0 = bA0, bA1 = bA0, bB1 = bA0;
    int   kA0 = 0, kB0 = 0, kA1 = 0, kB1 = 0;

    for (int j = 0; j < NBT; j++) {
        const int bufid = j % 3;
        MBAR_WAIT(mb + bufid * 8, (j / 3) & 1);    // tile step j landed
        __syncthreads();                           // all warps past step j-1's buffer
        if (tid == 0 && j + 2 < NBT) {
            int nb = (j + 2) % 3;
            MBAR_EXPECT_TX(mb + nb * 8, 16384);
            bulk_copy(sb + (uint32_t)nb * 16384,
                      g_ebuf + (size_t)((s + j + 2) & 15) * 16384, mb + nb * 8);
        }

        const int  tact = (s + j) & 15;            // actual codebook tile
        const char* buf = smem + (size_t)bufid * 16384;

#pragma unroll
        for (int nt2 = 0; nt2 < 4; nt2++) {
            const int  n0 = tact * BTILE + nt2 * 16;
            const char* bA = buf + nt2 * 2048 + r * 256;

            float2 nv0 = *(const float2*)(nsm + n0 + 2 * c0);
            float2 nv1 = *(const float2*)(nsm + n0 + 8 + 2 * c0);
            float hhA0[4] = { nv0.x, nv0.y, nv0.x, nv0.y };
            float hhA1[4] = { nv1.x, nv1.y, nv1.x, nv1.y };
            float hhB0[4] = { nv0.x, nv0.y, nv0.x, nv0.y };
            float hhB1[4] = { nv1.x, nv1.y, nv1.x, nv1.y };
            float xA0[4] = {0,0,0,0}, xA1[4] = {0,0,0,0};
            float xB0[4] = {0,0,0,0}, xB1[4] = {0,0,0,0};

#pragma unroll
            for (int ks = 0; ks < 4; ks++) {
                uint4 bh = *(const uint4*)(bA + kk[ks]);
                uint4 bl = *(const uint4*)(bA + kk[ks] + 8192);
                mma16(hhA0, AhA[ks], bh.x, bh.y);
                mma16(hhA1, AhA[ks], bh.z, bh.w);
                mma16(xA0,  AhA[ks], bl.x, bl.y);
                mma16(xA0,  AlA[ks], bh.x, bh.y);
                mma16(xA1,  AhA[ks], bl.z, bl.w);
                mma16(xA1,  AlA[ks], bh.z, bh.w);
                mma16(hhB0, AhB[ks], bh.x, bh.y);
                mma16(hhB1, AhB[ks], bh.z, bh.w);
                mma16(xB0,  AhB[ks], bl.x, bl.y);
                mma16(xB0,  AlB[ks], bh.x, bh.y);
                mma16(xB1,  AhB[ks], bl.z, bl.w);
                mma16(xB1,  AlB[ks], bh.z, bh.w);
            }

            // dist = norm + hh + x * 2^-11 ; strict < (order-invariant global min)
#pragma unroll
            for (int g = 0; g < 2; g++) {
                float* hh0 = g ? hhB0 : hhA0;
                float* hh1 = g ? hhB1 : hhA1;
                float* x0  = g ? xB0  : xA0;
                float* x1  = g ? xB1  : xA1;
                float& bA_ = g ? bA1 : bA0;  int& kA_ = g ? kA1 : kA0;
                float& bB_ = g ? bB1 : bB0;  int& kB_ = g ? kB1 : kB0;
                {
                    int e = n0 + 2 * c0;
                    float d0 = fmaf(x0[0], INV2048, hh0[0]);
                    float d1 = fmaf(x0[1], INV2048, hh0[1]);
                    float d2 = fmaf(x0[2], INV2048, hh0[2]);
                    float d3 = fmaf(x0[3], INV2048, hh0[3]);
                    if (d0 < bA_) { bA_ = d0; kA_ = e; }
                    if (d1 < bA_) { bA_ = d1; kA_ = e + 1; }
                    if (d2 < bB_) { bB_ = d2; kB_ = e; }
                    if (d3 < bB_) { bB_ = d3; kB_ = e + 1; }
                }
                {
                    int e = n0 + 8 + 2 * c0;
                    float d0 = fmaf(x1[0], INV2048, hh1[0]);
                    float d1 = fmaf(x1[1], INV2048, hh1[1]);
                    float d2 = fmaf(x1[2], INV2048, hh1[2]);
                    float d3 = fmaf(x1[3], INV2048, hh1[3]);
                    if (d0 < bA_) { bA_ = d0; kA_ = e; }
                    if (d1 < bA_) { bA_ = d1; kA_ = e + 1; }
                    if (d2 < bB_) { bB_ = d2; kB_ = e; }
                    if (d3 < bB_) { bB_ = d3; kB_ = e + 1; }
                }
            }
        }
    }

    // c0-lane reduce (tie-break smallest k)
#pragma unroll
    for (int off = 1; off <= 2; off <<= 1) {
        float vb; int vk;
        vb = __shfl_xor_sync(0xFFFFFFFFu, bA0, off); vk = __shfl_xor_sync(0xFFFFFFFFu, kA0, off);
        if (vb < bA0 || (vb == bA0 && vk < kA0)) { bA0 = vb; kA0 = vk; }
        vb = __shfl_xor_sync(0xFFFFFFFFu, bB0, off); vk = __shfl_xor_sync(0xFFFFFFFFu, kB0, off);
        if (vb < bB0 || (vb == bB0 && vk < kB0)) { bB0 = vb; kB0 = vk; }
        vb = __shfl_xor_sync(0xFFFFFFFFu, bA1, off); vk = __shfl_xor_sync(0xFFFFFFFFu, kA1, off);
        if (vb < bA1 || (vb == bA1 && vk < kA1)) { bA1 = vb; kA1 = vk; }
        vb = __shfl_xor_sync(0xFFFFFFFFu, bB1, off); vk = __shfl_xor_sync(0xFFFFFFFFu, kB1, off);
        if (vb < bB1 || (vb == bB1 && vk < kB1)) { bB1 = vb; kB1 = vk; }
    }
    if (c0 == 0) {
        sIdx[warp * 16 + r]          = kA0;
        sIdx[warp * 16 + r + 8]      = kB0;
        sIdx[64 + warp * 16 + r]     = kA1;
        sIdx[64 + warp * 16 + r + 8] = kB1;
    }
    __syncthreads();

    // gather winning codes (original fp32 emb) and scatter to [B,C,H,W]
    {
        const int pl = tid;
        const int k  = sIdx[pl];
        const float4* ev = (const float4*)(emb + (size_t)k * C_DIM);
        float* op = out + (size_t)b * C_DIM * HW + hw0 + pl;
#pragma unroll
        for (int c4 = 0; c4 < 16; c4++) {
            float4 v = ev[c4];
            op[(size_t)(c4 * 4 + 0) * HW] = v.x;
            op[(size_t)(c4 * 4 + 1) * HW] = v.y;
            op[(size_t)(c4 * 4 + 2) * HW] = v.z;
            op[(size_t)(c4 * 4 + 3) * HW] = v.w;
        }
    }
}

// ---------- launch ----------
extern "C" void kernel_launch(void* const* d_in, const int* in_sizes, int n_in,
                              void* d_out, int out_size)
{
    const float* z_e = (const float*)d_in[0];   // [32, 64, 64, 64]
    const float* emb = (const float*)d_in[1];   // [1024, 64]
    float*       out = (float*)d_out;

    cudaFuncSetAttribute(vq_mma, cudaFuncAttributeMaxDynamicSharedMemorySize, SM_TOT);

    prep<<<K_DIM / 64, 256>>>(emb);
    vq_mma<<<NPOS / MTILE, NTHREADS, SM_TOT>>>(z_e, emb, out);
}